// round 1
// baseline (speedup 1.0000x reference)
#include <cuda_runtime.h>
#include <math.h>

#define BB 2
#define NN 256
#define NODE_DIM 128
#define EDGE_DIM 256
#define HID 256
#define HH 8
#define DD 32
#define LN_EPS 1e-5f
#define OUT_EDGE_BASE (BB*NN*HID)

// ---------------- scratch (device globals; no allocations allowed) ----------
__device__ float d_h [BB*NN*HID];     // node projection (residual)
__device__ float d_q [BB*NN*HID];
__device__ float d_k [BB*NN*HID];
__device__ float d_v [BB*NN*HID];
__device__ float d_scores[BB*HH*NN*NN]; // scores -> attn (in place)
__device__ float d_am[BB*NN*NN];      // attn mean over heads
__device__ float d_ao[BB*NN*HID];     // attention output (pre-Wo)
__device__ float d_hp[BB*NN*HID];     // h_out @ Weo

// ---------------- 1. h = node @ Wn + bn ------------------------------------
__global__ void k_node_proj(const float* __restrict__ node,
                            const float* __restrict__ Wn,
                            const float* __restrict__ bn) {
    int row = blockIdx.x;          // [0, B*N)
    int c   = threadIdx.x;         // [0, HID)
    __shared__ float s[NODE_DIM];
    if (c < NODE_DIM) s[c] = node[row*NODE_DIM + c];
    __syncthreads();
    float acc = bn[c];
    #pragma unroll 8
    for (int k = 0; k < NODE_DIM; ++k) acc += s[k] * Wn[k*HID + c];
    d_h[row*HID + c] = acc;
}

// ---------------- 2. Q,K,V -------------------------------------------------
__global__ void k_qkv(const float* __restrict__ Wq, const float* __restrict__ bq,
                      const float* __restrict__ Wk, const float* __restrict__ bk,
                      const float* __restrict__ Wv, const float* __restrict__ bv) {
    int row = blockIdx.x;
    int c   = threadIdx.x;
    __shared__ float s[HID];
    s[c] = d_h[row*HID + c];
    __syncthreads();
    float aq = bq[c], ak = bk[c], av = bv[c];
    #pragma unroll 4
    for (int k = 0; k < HID; ++k) {
        float e = s[k];
        aq += e * Wq[k*HID + c];
        ak += e * Wk[k*HID + c];
        av += e * Wv[k*HID + c];
    }
    d_q[row*HID + c] = aq;
    d_k[row*HID + c] = ak;
    d_v[row*HID + c] = av;
}

// ---------------- 3. scores = QK^T / sqrt(D) --------------------------------
__global__ void k_scores() {
    int bid = blockIdx.x;                 // (b,h,n) : b*H*N + h*N + n
    int n = bid % NN;
    int h = (bid / NN) % HH;
    int b = bid / (NN * HH);
    int m = threadIdx.x;
    __shared__ float sq[DD];
    if (m < DD) sq[m] = d_q[(b*NN + n)*HID + h*DD + m];
    __syncthreads();
    const float* kr = &d_k[(b*NN + m)*HID + h*DD];
    float acc = 0.f;
    #pragma unroll
    for (int d = 0; d < DD; ++d) acc += sq[d] * kr[d];
    d_scores[bid*NN + m] = acc * 0.17677669529663687f;   // 1/sqrt(32)
}

// ---------------- 4. edge bias GEMM (THE big kernel) ------------------------
// For 32 edges (rows): p = E@Wep+bep, g = sigmoid(E@Weg+beg),
// edge_attn[row][h] = sum_d p*g ; accumulated into d_scores.
#define KC 16
__global__ void __launch_bounds__(256, 2)
k_edge_attn(const float* __restrict__ E,
            const float* __restrict__ Wep, const float* __restrict__ bep,
            const float* __restrict__ Weg, const float* __restrict__ beg) {
    __shared__ float sE [KC][32];
    __shared__ float sWp[KC][EDGE_DIM];
    __shared__ float sWg[KC][EDGE_DIM];
    __shared__ float sAcc[32][HH];

    int tid = threadIdx.x;
    int tx  = tid & 31;      // column group -> cols [tx*8, tx*8+8)
    int ty  = tid >> 5;      // row group    -> rows [ty*4, ty*4+4)
    int row0 = blockIdx.x * 32;

    float accP[4][8], accG[4][8];
    #pragma unroll
    for (int r = 0; r < 4; ++r)
        #pragma unroll
        for (int c = 0; c < 8; ++c) { accP[r][c] = 0.f; accG[r][c] = 0.f; }

    for (int kb = 0; kb < EDGE_DIM; kb += KC) {
        // E tile: 32 rows x KC
        #pragma unroll
        for (int i = 0; i < 2; ++i) {
            int lin = tid + i*256;
            int r = lin >> 4, k = lin & 15;
            sE[k][r] = E[(row0 + r)*EDGE_DIM + kb + k];
        }
        // weight tiles: KC x 256, column = tid (fully coalesced)
        #pragma unroll
        for (int k = 0; k < KC; ++k) {
            sWp[k][tid] = Wep[(kb + k)*EDGE_DIM + tid];
            sWg[k][tid] = Weg[(kb + k)*EDGE_DIM + tid];
        }
        __syncthreads();
        #pragma unroll
        for (int k = 0; k < KC; ++k) {
            float4 a  = *(const float4*)&sE [k][ty*4];
            float4 p0 = *(const float4*)&sWp[k][tx*8];
            float4 p1 = *(const float4*)&sWp[k][tx*8 + 4];
            float4 q0 = *(const float4*)&sWg[k][tx*8];
            float4 q1 = *(const float4*)&sWg[k][tx*8 + 4];
            float av[4] = {a.x, a.y, a.z, a.w};
            float pv[8] = {p0.x, p0.y, p0.z, p0.w, p1.x, p1.y, p1.z, p1.w};
            float gv[8] = {q0.x, q0.y, q0.z, q0.w, q1.x, q1.y, q1.z, q1.w};
            #pragma unroll
            for (int r = 0; r < 4; ++r)
                #pragma unroll
                for (int c = 0; c < 8; ++c) {
                    accP[r][c] += av[r] * pv[c];
                    accG[r][c] += av[r] * gv[c];
                }
        }
        __syncthreads();
    }

    // epilogue: bias + sigmoid + gated per-head reduction
    sAcc[tid >> 3][tid & 7] = 0.f;
    __syncthreads();
    int c0   = tx * 8;
    int head = c0 >> 5;     // 8 contiguous cols always within one head
    #pragma unroll
    for (int r = 0; r < 4; ++r) {
        float s = 0.f;
        #pragma unroll
        for (int c = 0; c < 8; ++c) {
            float p = accP[r][c] + bep[c0 + c];
            float g = accG[r][c] + beg[c0 + c];
            g = 1.f / (1.f + expf(-g));
            s += p * g;
        }
        atomicAdd(&sAcc[ty*4 + r][head], s);
    }
    __syncthreads();
    {
        int r = tid >> 3, h = tid & 7;
        int grow = row0 + r;                 // (b,n,m) flattened
        int m = grow & 255, n = (grow >> 8) & 255, b = grow >> 16;
        d_scores[((b*HH + h)*NN + n)*NN + m] += sAcc[r][h];
    }
}

// ---------------- 5. masked softmax (in place) -------------------------------
__global__ void k_softmax(const int* __restrict__ adj) {
    int bid = blockIdx.x;                 // (b,h,n)
    int n = bid % NN;
    int b = bid / (NN * HH);
    int m = threadIdx.x;
    float sc = d_scores[bid*NN + m];
    if (adj[(b*NN + n)*NN + m] == 0) sc = -1e9f;
    __shared__ float red[256];
    red[m] = sc; __syncthreads();
    for (int s = 128; s > 0; s >>= 1) { if (m < s) red[m] = fmaxf(red[m], red[m+s]); __syncthreads(); }
    float mx = red[0]; __syncthreads();
    float e = expf(sc - mx);
    red[m] = e; __syncthreads();
    for (int s = 128; s > 0; s >>= 1) { if (m < s) red[m] += red[m+s]; __syncthreads(); }
    d_scores[bid*NN + m] = e / red[0];
}

// ---------------- 6. attention mean over heads -------------------------------
__global__ void k_attn_mean() {
    int idx = blockIdx.x * 256 + threadIdx.x;   // (b,n,m)
    int m = idx & 255, n = (idx >> 8) & 255, b = idx >> 16;
    float s = 0.f;
    #pragma unroll
    for (int h = 0; h < HH; ++h) s += d_scores[((b*HH + h)*NN + n)*NN + m];
    d_am[idx] = s * (1.f / HH);
}

// ---------------- 7. attn_out = attn @ V -------------------------------------
__global__ void k_attn_out() {
    int row = blockIdx.x;                 // (b,n)
    int b = row >> 8;
    int n = row & 255;
    __shared__ float sA[HH][NN];          // 8KB
    for (int i = threadIdx.x; i < HH*NN; i += 256) {
        int h = i >> 8, m = i & 255;
        sA[h][m] = d_scores[((b*HH + h)*NN + n)*NN + m];
    }
    __syncthreads();
    int c = threadIdx.x;
    int h = c >> 5;
    float acc = 0.f;
    #pragma unroll 4
    for (int m = 0; m < NN; ++m) acc += sA[h][m] * d_v[(b*NN + m)*HID + c];
    d_ao[row*HID + c] = acc;
}

// ---------------- 8. h_out = LN(residual + attn_out@Wo + bo) ------------------
__global__ void k_hout(const float* __restrict__ Wo, const float* __restrict__ bo,
                       const float* __restrict__ g1, const float* __restrict__ b1,
                       float* __restrict__ out) {
    int row = blockIdx.x;
    int c   = threadIdx.x;
    __shared__ float s[HID];
    __shared__ float red[256];
    s[c] = d_ao[row*HID + c];
    __syncthreads();
    float acc = bo[c];
    #pragma unroll 4
    for (int k = 0; k < HID; ++k) acc += s[k] * Wo[k*HID + c];
    float y = acc + d_h[row*HID + c];
    red[c] = y; __syncthreads();
    for (int st = 128; st > 0; st >>= 1) { if (c < st) red[c] += red[c+st]; __syncthreads(); }
    float mean = red[0] * (1.f / HID); __syncthreads();
    float dlt = y - mean;
    red[c] = dlt * dlt; __syncthreads();
    for (int st = 128; st > 0; st >>= 1) { if (c < st) red[c] += red[c+st]; __syncthreads(); }
    float var = red[0] * (1.f / HID);
    out[row*HID + c] = (y - mean) * rsqrtf(var + LN_EPS) * g1[c] + b1[c];
}

// ---------------- 9. hp = h_out @ Weo -----------------------------------------
__global__ void k_hp(const float* __restrict__ out, const float* __restrict__ Weo) {
    int row = blockIdx.x;
    int c   = threadIdx.x;
    __shared__ float s[HID];
    s[c] = out[row*HID + c];
    __syncthreads();
    float acc = 0.f;
    #pragma unroll 4
    for (int k = 0; k < HID; ++k) acc += s[k] * Weo[k*EDGE_DIM + c];
    d_hp[row*EDGE_DIM + c] = acc;
}

// ---------------- 10. edge_out = LN(E + am*0.5*(hp_n+hp_m) + beo) --------------
// one warp per edge, warp-shuffle LN (no block barriers)
__global__ void k_edge_out(const float* __restrict__ E,
                           const float* __restrict__ beo,
                           const float* __restrict__ g2,
                           const float* __restrict__ b2,
                           float* __restrict__ out) {
    int w = blockIdx.x * 8 + (threadIdx.x >> 5);   // edge (b,n,m) flattened
    int lane = threadIdx.x & 31;
    int m = w & 255, n = (w >> 8) & 255, b = w >> 16;
    float am = d_am[w] * 0.5f;
    const float* Er = &E[(size_t)w * EDGE_DIM];
    const float* hn = &d_hp[(b*NN + n)*EDGE_DIM];
    const float* hm = &d_hp[(b*NN + m)*EDGE_DIM];
    float x[8];
    float s = 0.f, s2 = 0.f;
    #pragma unroll
    for (int j = 0; j < 8; ++j) {
        int c = j*32 + lane;
        float v = Er[c] + am * (hn[c] + hm[c]) + beo[c];
        x[j] = v; s += v; s2 += v * v;
    }
    #pragma unroll
    for (int o = 16; o > 0; o >>= 1) {
        s  += __shfl_xor_sync(0xffffffffu, s,  o);
        s2 += __shfl_xor_sync(0xffffffffu, s2, o);
    }
    float mean = s * (1.f / EDGE_DIM);
    float var  = s2 * (1.f / EDGE_DIM) - mean * mean;
    float rinv = rsqrtf(var + LN_EPS);
    float* op = &out[OUT_EDGE_BASE + (size_t)w * EDGE_DIM];
    #pragma unroll
    for (int j = 0; j < 8; ++j) {
        int c = j*32 + lane;
        op[c] = (x[j] - mean) * rinv * g2[c] + b2[c];
    }
}

// ---------------- launch ------------------------------------------------------
extern "C" void kernel_launch(void* const* d_in, const int* in_sizes, int n_in,
                              void* d_out, int out_size) {
    const float* node = (const float*)d_in[0];
    const float* E    = (const float*)d_in[1];
    const int*   adj  = (const int*)  d_in[2];
    const float* Wn  = (const float*)d_in[3];  const float* bn  = (const float*)d_in[4];
    const float* Wq  = (const float*)d_in[5];  const float* bq  = (const float*)d_in[6];
    const float* Wk  = (const float*)d_in[7];  const float* bk  = (const float*)d_in[8];
    const float* Wv  = (const float*)d_in[9];  const float* bv  = (const float*)d_in[10];
    const float* Wep = (const float*)d_in[11]; const float* bep = (const float*)d_in[12];
    const float* Weg = (const float*)d_in[13]; const float* beg = (const float*)d_in[14];
    const float* Wo  = (const float*)d_in[15]; const float* bo  = (const float*)d_in[16];
    const float* Weo = (const float*)d_in[17]; const float* beo = (const float*)d_in[18];
    const float* g1  = (const float*)d_in[19]; const float* b1  = (const float*)d_in[20];
    const float* g2  = (const float*)d_in[21]; const float* b2  = (const float*)d_in[22];
    float* out = (float*)d_out;

    k_node_proj<<<BB*NN, HID>>>(node, Wn, bn);
    k_qkv      <<<BB*NN, HID>>>(Wq, bq, Wk, bk, Wv, bv);
    k_scores   <<<BB*HH*NN, NN>>>();
    k_edge_attn<<<BB*NN*NN/32, 256>>>(E, Wep, bep, Weg, beg);
    k_softmax  <<<BB*HH*NN, NN>>>(adj);
    k_attn_mean<<<BB*NN*NN/256, 256>>>();
    k_attn_out <<<BB*NN, HID>>>();
    k_hout     <<<BB*NN, HID>>>(Wo, bo, g1, b1, out);
    k_hp       <<<BB*NN, EDGE_DIM>>>(out, Weo);
    k_edge_out <<<BB*NN*NN/8, 256>>>(E, beo, g2, b2, out);
}